// round 3
// baseline (speedup 1.0000x reference)
#include <cuda_runtime.h>

// Output depends ONLY on frame[0, :, :] (32 chirps x 64 samples).
// Single-CTA kernel: windows + twiddle tables in smem, brute-force DFTs.
// Output dtype: float32 (values equal to the reference's uint8 pixels).

#define NC 32
#define NS 64
#define PI_F 3.14159265358979323846f

__global__ __launch_bounds__(1024) void rdm_kernel(const float* __restrict__ frame,
                                                   float* __restrict__ out)
{
    __shared__ float s_x[NC][NS];          // mean-removed, range-windowed signal
    __shared__ float s_rw[NS];             // hann window (unnormalized)
    __shared__ float s_dw[NC];             // kaiser window (unnormalized)
    __shared__ float s_mean[NC];           // per-chirp mean
    __shared__ float s_Xre[NC][NC + 1];    // range-FFT bins 0..31 (pad vs conflicts)
    __shared__ float s_Xim[NC][NC + 1];
    __shared__ float s_cmre[NC];           // MTI chirp-mean per range bin
    __shared__ float s_cmim[NC];
    __shared__ float s_t64r[NS], s_t64i[NS];  // exp(-2*pi*i*j/64)
    __shared__ float s_t32r[NC], s_t32i[NC];  // exp(-2*pi*i*j/32)
    __shared__ float s_rwsum, s_dwsum;

    const int tid = threadIdx.x;

    // ---- init: windows, twiddles, chirp means (disjoint thread ranges) ----
    if (tid < NS) {
        // hann_window(64, periodic=False)
        s_rw[tid] = 0.5f - 0.5f * cosf(2.0f * PI_F * (float)tid / (float)(NS - 1));
    }
    if (tid >= 64 && tid < 96) {
        int n = tid - 64;
        float alpha = (float)(NC - 1) * 0.5f;
        float t = ((float)n - alpha) / alpha;
        float arg = 1.0f - t * t;
        s_dw[n] = cyl_bessel_i0f(25.0f * sqrtf(fmaxf(arg, 0.0f))) / cyl_bessel_i0f(25.0f);
    }
    if (tid >= 128 && tid < 192) {
        int j = tid - 128;
        float sn, cs;
        sincosf(-2.0f * PI_F * (float)j / (float)NS, &sn, &cs);
        s_t64r[j] = cs; s_t64i[j] = sn;
    }
    if (tid >= 192 && tid < 224) {
        int j = tid - 192;
        float sn, cs;
        sincosf(-2.0f * PI_F * (float)j / (float)NC, &sn, &cs);
        s_t32r[j] = cs; s_t32i[j] = sn;
    }
    if (tid >= 224 && tid < 256) {
        int c = tid - 224;
        float s = 0.0f;
        #pragma unroll
        for (int i = 0; i < NS; i++) s += frame[c * NS + i];
        s_mean[c] = s * (1.0f / (float)NS);
    }
    __syncthreads();

    if (tid == 0) { float s = 0.0f; for (int i = 0; i < NS; i++) s += s_rw[i]; s_rwsum = s; }
    if (tid == 1) { float s = 0.0f; for (int i = 0; i < NC; i++) s += s_dw[i]; s_dwsum = s; }
    __syncthreads();

    // ---- windowed input ----
    {
        float rwn = 1.0f / s_rwsum;
        for (int idx = tid; idx < NC * NS; idx += 1024) {
            int c = idx >> 6, s = idx & 63;
            s_x[c][s] = (frame[idx] - s_mean[c]) * (s_rw[s] * rwn);
        }
    }
    __syncthreads();

    // ---- range DFT: thread (c, k); X[k] = sum_s x[s] * exp(-2*pi*i*k*s/64) ----
    {
        int c = tid >> 5, k = tid & 31;
        float re = 0.0f, im = 0.0f;
        #pragma unroll
        for (int s = 0; s < NS; s++) {
            int j = (k * s) & (NS - 1);
            float v = s_x[c][s];
            re = fmaf(v, s_t64r[j], re);
            im = fmaf(v, s_t64i[j], im);
        }
        s_Xre[c][k] = re;
        s_Xim[c][k] = im;
    }
    __syncthreads();

    // ---- MTI chirp means per range bin ----
    if (tid < NC) {
        float sr = 0.0f, si = 0.0f;
        #pragma unroll
        for (int c = 0; c < NC; c++) { sr += s_Xre[c][tid]; si += s_Xim[c][tid]; }
        s_cmre[tid] = sr * (1.0f / (float)NC);
        s_cmim[tid] = si * (1.0f / (float)NC);
    }
    __syncthreads();

    // ---- doppler DFT + epilogue: thread (d, k) ----
    {
        int d = tid >> 5, k = tid & 31;
        float dwn = 1.0f / s_dwsum;
        float zre = 0.0f, zim = 0.0f;
        #pragma unroll
        for (int c = 0; c < NC; c++) {
            float w = s_dw[c] * dwn;
            float ar = (s_Xre[c][k] - s_cmre[k]) * w;
            float ai = (s_Xim[c][k] - s_cmim[k]) * w;
            int j = (d * c) & (NC - 1);
            float cs = s_t32r[j], sn = s_t32i[j];
            zre += ar * cs - ai * sn;
            zim += ar * sn + ai * cs;
        }
        float mag = sqrtf(zre * zre + zim * zim) * 1000.0f;
        float v = fminf(fmaxf(mag, 0.0f), 1.0f) * 255.0f;
        // match numpy astype(uint8): truncation toward zero, then store as float
        float q = truncf(v);
        int m = (d + 16) & (NC - 1);            // fftshift along doppler
        out[(31 - k) * 32 + m] = q;             // transpose + flip(range)
    }
}

extern "C" void kernel_launch(void* const* d_in, const int* in_sizes, int n_in,
                              void* d_out, int out_size)
{
    (void)in_sizes; (void)n_in; (void)out_size;
    const float* frame = (const float*)d_in[0];
    float* out = (float*)d_out;
    rdm_kernel<<<1, 1024>>>(frame, out);
}

// round 4
// speedup vs baseline: 2.3646x; 2.3646x over previous
#include <cuda_runtime.h>

// All constants baked at compile time via constexpr double-precision math.
// Output depends only on frame[0] (32 chirps x 64 samples). Single CTA.

struct Tab {
    float rt_r[2048], rt_i[2048];  // [k][s] hann-normalized range twiddles
    float rk_r[32],   rk_i[32];    // row sums (mean-removal correction)
    float dt_r[1024], dt_i[1024];  // [d][c] kaiser-normalized doppler twiddles
    float wd_r[32],   wd_i[32];    // row sums (MTI correction)
};

constexpr double PI_D = 3.14159265358979323846264338327950288;

constexpr double d_sin(double x) {
    double t = x, s = x, x2 = x * x;
    for (int n = 1; n <= 11; ++n) { t *= -x2 / double((2*n)*(2*n+1)); s += t; }
    return s;
}
constexpr double d_cos(double x) {
    double t = 1.0, s = 1.0, x2 = x * x;
    for (int n = 1; n <= 11; ++n) { t *= -x2 / double((2*n-1)*(2*n)); s += t; }
    return s;
}
constexpr double d_sqrt(double x) {
    if (x <= 0.0) return 0.0;
    double r = x > 1.0 ? x : 1.0;
    for (int i = 0; i < 40; ++i) r = 0.5 * (r + x / r);
    return r;
}
constexpr double d_i0(double x) {
    double t = 1.0, s = 1.0, q = x * 0.5;
    for (int m = 1; m <= 70; ++m) { double u = q / m; t *= u * u; s += t; }
    return s;
}
constexpr double red(double a) {  // wrap into [-pi, pi]
    while (a < -PI_D) a += 2.0 * PI_D;
    while (a >  PI_D) a -= 2.0 * PI_D;
    return a;
}

constexpr Tab make_tab() {
    Tab T{};
    // hann(64, periodic=False), unit sum
    double rw[64] = {}; double rsum = 0.0;
    for (int n = 0; n < 64; ++n) {
        rw[n] = 0.5 - 0.5 * d_cos(red(2.0 * PI_D * n / 63.0));
        rsum += rw[n];
    }
    for (int n = 0; n < 64; ++n) rw[n] /= rsum;
    // kaiser(32, beta=25), unit sum
    double dw[32] = {}; double dsum = 0.0; double i025 = d_i0(25.0);
    for (int n = 0; n < 32; ++n) {
        double al = 15.5, tt = (n - al) / al;
        double arg = 1.0 - tt * tt;
        dw[n] = d_i0(25.0 * d_sqrt(arg < 0.0 ? 0.0 : arg)) / i025;
        dsum += dw[n];
    }
    for (int n = 0; n < 32; ++n) dw[n] /= dsum;
    // range: rt[k][s] = rw[s] * exp(-2*pi*i*(k*s mod 64)/64); rk[k] = row sum
    for (int k = 0; k < 32; ++k) {
        double sr = 0.0, si = 0.0;
        for (int s = 0; s < 64; ++s) {
            double ang = red(-2.0 * PI_D * double((k * s) & 63) / 64.0);
            double cr = d_cos(ang), ci = d_sin(ang);
            T.rt_r[k*64+s] = (float)(rw[s] * cr);
            T.rt_i[k*64+s] = (float)(rw[s] * ci);
            sr += rw[s] * cr; si += rw[s] * ci;
        }
        T.rk_r[k] = (float)sr; T.rk_i[k] = (float)si;
    }
    // doppler: dt[d][c] = dw[c] * exp(-2*pi*i*(d*c mod 32)/32); wd[d] = row sum
    for (int d = 0; d < 32; ++d) {
        double sr = 0.0, si = 0.0;
        for (int c = 0; c < 32; ++c) {
            double ang = red(-2.0 * PI_D * double((d * c) & 31) / 32.0);
            double cr = d_cos(ang), ci = d_sin(ang);
            T.dt_r[d*32+c] = (float)(dw[c] * cr);
            T.dt_i[d*32+c] = (float)(dw[c] * ci);
            sr += dw[c] * cr; si += dw[c] * ci;
        }
        T.wd_r[d] = (float)sr; T.wd_i[d] = (float)si;
    }
    return T;
}

__device__ const Tab g_tab = make_tab();

#define TAB_FLOATS 6272

__global__ __launch_bounds__(1024) void rdm_kernel(const float* __restrict__ frame,
                                                   float* __restrict__ out)
{
    __shared__ float s_tab[TAB_FLOATS];
    __shared__ float s_x[32 * 65];     // [c][s], pad 65: banks (c+s)%32
    __shared__ float s_Xr[32 * 33];    // [k][c], pad 33
    __shared__ float s_Xi[32 * 33];
    __shared__ float s_img[32 * 33];

    const int tid  = threadIdx.x;
    const int lane = tid & 31;
    const int warp = tid >> 5;

    // stage tables (coalesced LDG from __device__ const global)
    const float* gt = (const float*)&g_tab;
    #pragma unroll
    for (int i = 0; i < 7; ++i) {
        int idx = tid + i * 1024;
        if (idx < TAB_FLOATS) s_tab[idx] = gt[idx];
    }
    // stage frame[0]: [c][s] -> padded smem
    #pragma unroll
    for (int i = 0; i < 2; ++i) {
        int idx = tid + i * 1024;               // 0..2047
        s_x[(idx >> 6) * 65 + (idx & 63)] = frame[idx];
    }
    __syncthreads();

    const float* RTr = s_tab;
    const float* RTi = s_tab + 2048;
    const float* RKr = s_tab + 4096;
    const float* RKi = s_tab + 4128;
    const float* DTr = s_tab + 4160;
    const float* DTi = s_tab + 5184;
    const float* WDr = s_tab + 6208;
    const float* WDi = s_tab + 6240;

    // ---- stage 1: range DFT. warp = k (uniform twiddles), lane = c ----
    {
        const int k = warp, c = lane;
        const float* xr = s_x + c * 65;
        const float* tr = RTr + k * 64;
        const float* ti = RTi + k * 64;
        float ar = 0.0f, ai = 0.0f, sx = 0.0f;
        #pragma unroll
        for (int s = 0; s < 64; ++s) {
            float v = xr[s];
            ar = fmaf(v, tr[s], ar);
            ai = fmaf(v, ti[s], ai);
            sx += v;
        }
        float m = sx * 0.015625f;                   // per-chirp mean
        s_Xr[k * 33 + c] = ar - m * RKr[k];         // folded mean removal
        s_Xi[k * 33 + c] = ai - m * RKi[k];
    }
    __syncthreads();

    // ---- stage 2: doppler DFT + MTI fold + epilogue. warp = d, lane = k ----
    {
        const int d = warp, k = lane;
        const float* ctr = DTr + d * 32;
        const float* cti = DTi + d * 32;
        float zr = 0.0f, zi = 0.0f, sr = 0.0f, si = 0.0f;
        #pragma unroll
        for (int c = 0; c < 32; ++c) {
            float xre = s_Xr[k * 33 + c];
            float xim = s_Xi[k * 33 + c];
            float a = ctr[c], b = cti[c];
            zr = fmaf(xre, a, fmaf(-xim, b, zr));
            zi = fmaf(xre, b, fmaf(xim, a, zi));
            sr += xre; si += xim;
        }
        float mr = sr * 0.03125f, mi = si * 0.03125f;   // MTI chirp mean
        float wr = WDr[d], wi = WDi[d];
        zr -= mr * wr - mi * wi;
        zi -= mr * wi + mi * wr;
        float mag = sqrtf(zr * zr + zi * zi) * 1000.0f;
        float v = fminf(fmaxf(mag, 0.0f), 1.0f) * 255.0f;
        s_img[(31 - k) * 33 + ((d + 16) & 31)] = truncf(v);  // shift+transpose+flip
    }
    __syncthreads();

    // coalesced output
    out[tid] = s_img[(tid >> 5) * 33 + (tid & 31)];
}

extern "C" void kernel_launch(void* const* d_in, const int* in_sizes, int n_in,
                              void* d_out, int out_size)
{
    (void)in_sizes; (void)n_in; (void)out_size;
    rdm_kernel<<<1, 1024>>>((const float*)d_in[0], (float*)d_out);
}

// round 5
// speedup vs baseline: 2.4170x; 1.0221x over previous
#include <cuda_runtime.h>

// Single CTA, 256 threads. All constants compile-time baked, mean-removal and
// MTI folded into twiddle tables. Packed f32x2 FMAs, swizzled conflict-free smem.

typedef unsigned long long u64;

constexpr double PI_D = 3.14159265358979323846264338327950288;

constexpr double d_sin(double x) {
    double t = x, s = x, x2 = x * x;
    for (int n = 1; n <= 11; ++n) { t *= -x2 / double((2*n)*(2*n+1)); s += t; }
    return s;
}
constexpr double d_cos(double x) {
    double t = 1.0, s = 1.0, x2 = x * x;
    for (int n = 1; n <= 11; ++n) { t *= -x2 / double((2*n-1)*(2*n)); s += t; }
    return s;
}
constexpr double d_sqrt(double x) {
    if (x <= 0.0) return 0.0;
    double r = x > 1.0 ? x : 1.0;
    for (int i = 0; i < 40; ++i) r = 0.5 * (r + x / r);
    return r;
}
constexpr double d_i0(double x) {
    double t = 1.0, s = 1.0, q = x * 0.5;
    for (int m = 1; m <= 70; ++m) { double u = q / m; t *= u * u; s += t; }
    return s;
}
constexpr double red(double a) {
    while (a < -PI_D) a += 2.0 * PI_D;
    while (a >  PI_D) a -= 2.0 * PI_D;
    return a;
}

struct alignas(16) Tab {
    // t1[s][k][2]: rw[s]*exp(-2pi*i*k*s/64) - RK[k]/64   (hann + mean-removal fold)
    float t1[64][32][2];
    // t2[c][d][4]: (a, b, b, a) with a+ib = dw[c]*exp(-2pi*i*d*c/32) - WD[d]/32
    float t2[32][32][4];
};

constexpr Tab make_tab() {
    Tab T{};
    // hann(64, periodic=False), unit sum
    double rw[64] = {}; double rsum = 0.0;
    for (int n = 0; n < 64; ++n) { rw[n] = 0.5 - 0.5 * d_cos(red(2.0*PI_D*n/63.0)); rsum += rw[n]; }
    for (int n = 0; n < 64; ++n) rw[n] /= rsum;
    // kaiser(32, beta=25), unit sum
    double dw[32] = {}; double dsum = 0.0; double i025 = d_i0(25.0);
    for (int n = 0; n < 32; ++n) {
        double al = 15.5, tt = (n - al) / al, arg = 1.0 - tt*tt;
        dw[n] = d_i0(25.0 * d_sqrt(arg < 0.0 ? 0.0 : arg)) / i025; dsum += dw[n];
    }
    for (int n = 0; n < 32; ++n) dw[n] /= dsum;
    // range table + fold
    for (int k = 0; k < 32; ++k) {
        double rkr = 0.0, rki = 0.0;
        for (int s = 0; s < 64; ++s) {
            double ang = red(-2.0*PI_D*double((k*s)&63)/64.0);
            rkr += rw[s]*d_cos(ang); rki += rw[s]*d_sin(ang);
        }
        for (int s = 0; s < 64; ++s) {
            double ang = red(-2.0*PI_D*double((k*s)&63)/64.0);
            T.t1[s][k][0] = (float)(rw[s]*d_cos(ang) - rkr/64.0);
            T.t1[s][k][1] = (float)(rw[s]*d_sin(ang) - rki/64.0);
        }
    }
    // doppler table + MTI fold
    for (int d = 0; d < 32; ++d) {
        double wdr = 0.0, wdi = 0.0;
        for (int c = 0; c < 32; ++c) {
            double ang = red(-2.0*PI_D*double((d*c)&31)/32.0);
            wdr += dw[c]*d_cos(ang); wdi += dw[c]*d_sin(ang);
        }
        for (int c = 0; c < 32; ++c) {
            double ang = red(-2.0*PI_D*double((d*c)&31)/32.0);
            double a = dw[c]*d_cos(ang) - wdr/32.0;
            double b = dw[c]*d_sin(ang) - wdi/32.0;
            T.t2[c][d][0] = (float)a; T.t2[c][d][1] = (float)b;
            T.t2[c][d][2] = (float)b; T.t2[c][d][3] = (float)a;
        }
    }
    return T;
}

__device__ const Tab g_tab = make_tab();

__device__ __forceinline__ u64 pk(float lo, float hi) {
    u64 r; asm("mov.b64 %0, {%1,%2};" : "=l"(r) : "f"(lo), "f"(hi)); return r;
}
__device__ __forceinline__ void upk(u64 v, float& lo, float& hi) {
    asm("mov.b64 {%0,%1}, %2;" : "=f"(lo), "=f"(hi) : "l"(v));
}
__device__ __forceinline__ u64 ffma2(u64 a, u64 b, u64 c) {
    u64 d; asm("fma.rn.f32x2 %0, %1, %2, %3;" : "=l"(d) : "l"(a), "l"(b), "l"(c)); return d;
}

// smem pool: 12288 floats = 48KB exactly
//  [    0, 4096)  T1  (img overlays this in stage 2: 1056 floats)
//  [ 4096, 8192)  T2
//  [ 8192,10240)  X   (32c x 32k complex, u64 each, col-swizzled (k+c)&31)
//  [10240,12288)  xw  (32c x 64s, col-swizzled (s+c)&63)
#define T1_OFF 0
#define T2_OFF 4096
#define X_OFF  8192
#define XW_OFF 10240

__global__ __launch_bounds__(256) void rdm_kernel(const float* __restrict__ frame,
                                                  float* __restrict__ out)
{
    __shared__ __align__(16) float pool[12288];

    const int tid  = threadIdx.x;
    const int lane = tid & 31;
    const int warp = tid >> 5;

    // ---- stage tables (coalesced, 32KB) ----
    {
        const float4* src = (const float4*)&g_tab;
        float4* dst = (float4*)pool;
        #pragma unroll
        for (int i = 0; i < 8; ++i) dst[tid + i * 256] = src[tid + i * 256];
    }
    // ---- stage frame[0] with (s+c)&63 swizzle ----
    #pragma unroll
    for (int i = 0; i < 8; ++i) {
        int idx = tid + i * 256;            // 0..2047
        int c = idx >> 6, s = idx & 63;
        pool[XW_OFF + c * 64 + ((s + c) & 63)] = frame[idx];
    }
    __syncthreads();

    // ---- stage 1: range DFT. warp -> k = 4*warp..+3, lane = c ----
    {
        const int c = lane, k4 = warp << 2;
        const float* xrow = pool + XW_OFF + c * 64;
        u64 a0 = 0, a1 = 0, a2 = 0, a3 = 0;
        #pragma unroll
        for (int s = 0; s < 64; ++s) {
            float v = xrow[(s + c) & 63];
            u64 vv = pk(v, v);
            const ulonglong2* tp = (const ulonglong2*)(pool + T1_OFF + ((s << 5) + k4) * 2);
            ulonglong2 tA = tp[0];   // twiddles for k4+0, k4+1 (pre-packed complex)
            ulonglong2 tB = tp[1];   // k4+2, k4+3
            a0 = ffma2(vv, tA.x, a0);
            a1 = ffma2(vv, tA.y, a1);
            a2 = ffma2(vv, tB.x, a2);
            a3 = ffma2(vv, tB.y, a3);
        }
        u64* Xp = (u64*)(pool + X_OFF);
        Xp[c * 32 + ((k4 + 0 + c) & 31)] = a0;
        Xp[c * 32 + ((k4 + 1 + c) & 31)] = a1;
        Xp[c * 32 + ((k4 + 2 + c) & 31)] = a2;
        Xp[c * 32 + ((k4 + 3 + c) & 31)] = a3;
    }
    __syncthreads();

    // ---- stage 2: doppler DFT (+folded MTI) + epilogue. warp -> d = 4*warp..+3, lane = k ----
    {
        const int k = lane, d4 = warp << 2;
        u64 z0 = 0, z1 = 0, z2 = 0, z3 = 0;
        const float2* Xp = (const float2*)(pool + X_OFF);
        #pragma unroll
        for (int c = 0; c < 32; ++c) {
            float2 X = Xp[c * 32 + ((k + c) & 31)];
            u64 v1 = pk(X.x, X.x);
            u64 v2 = pk(-X.y, X.y);
            const ulonglong2* tp = (const ulonglong2*)(pool + T2_OFF + ((c << 5) + d4) * 4);
            ulonglong2 tA = tp[0];   // d4+0: (a,b),(b,a)
            ulonglong2 tB = tp[1];   // d4+1
            ulonglong2 tC = tp[2];   // d4+2
            ulonglong2 tD = tp[3];   // d4+3
            z0 = ffma2(v1, tA.x, ffma2(v2, tA.y, z0));
            z1 = ffma2(v1, tB.x, ffma2(v2, tB.y, z1));
            z2 = ffma2(v1, tC.x, ffma2(v2, tC.y, z2));
            z3 = ffma2(v1, tD.x, ffma2(v2, tD.y, z3));
        }
        float* img = pool + T1_OFF;   // T1 dead now
        u64 zz[4] = {z0, z1, z2, z3};
        #pragma unroll
        for (int dd = 0; dd < 4; ++dd) {
            float zr, zi; upk(zz[dd], zr, zi);
            float mag = sqrtf(zr * zr + zi * zi) * 1000.0f;
            float v = fminf(fmaxf(mag, 0.0f), 1.0f) * 255.0f;
            img[(31 - k) * 33 + ((d4 + dd + 16) & 31)] = truncf(v);
        }
    }
    __syncthreads();

    // ---- coalesced float4 output ----
    {
        const float* img = pool + T1_OFF;
        int i = tid << 2;
        int row = i >> 5, col = i & 31;
        float4 o;
        o.x = img[row * 33 + col + 0];
        o.y = img[row * 33 + col + 1];
        o.z = img[row * 33 + col + 2];
        o.w = img[row * 33 + col + 3];
        ((float4*)out)[tid] = o;
    }
}

extern "C" void kernel_launch(void* const* d_in, const int* in_sizes, int n_in,
                              void* d_out, int out_size)
{
    (void)in_sizes; (void)n_in; (void)out_size;
    rdm_kernel<<<1, 256>>>((const float*)d_in[0], (float*)d_out);
}